// round 17
// baseline (speedup 1.0000x reference)
#include <cuda_runtime.h>
#include <cuda_fp16.h>
#include <mma.h>
#include <cstdint>
#include <cstddef>

using namespace nvcuda;

#define NN   16384
#define DF   256
#define KCAT 512
#define NSLC 8
#define SLC_ITERS 32

// ---------------- device-global scratch ----------------
__device__ __half g_ftT[(size_t)DF * NN];        // features^T fp16
__device__ __half g_cat[(size_t)NN * KCAT];      // features in cols 0..255 (neigh half unused now)
__device__ __half g_w[(size_t)DF * KCAT];        // W fp16
__device__ __half g_part[(size_t)NSLC * NN * DF];// P partials fp16 [8][16384][256]
__device__ float  g_rs[(size_t)NSLC * NN];       // rowsum partials

// ---------------- k_main smem (frozen R15) ----------------
constexpr int ASTM = 72;
constexpr int A_STG = 128 * ASTM * 2;
constexpr int B_STG = 256 * ASTM * 2;
constexpr int OFF_BM = 2 * A_STG;
constexpr int SMEM_MAIN = OFF_BM + 3 * B_STG;  // 147456

// ---------------- k_out smem: BM=64, 4-stage, 2 CTAs/SM ----------------
constexpr int AST = 40;
constexpr int AO_STG = 64 * AST * 2;           // 5120
constexpr int BO_STG = 256 * AST * 2;          // 20480
constexpr int OFF_BO = 4 * AO_STG;             // 20480
constexpr int OFF_SIV = OFF_BO + 4 * BO_STG;   // 102400
constexpr int SST = 68;
constexpr int SMEM_OUT = OFF_SIV + 256;        // 102656 (x2 = 205312 < 228KB)

__device__ __forceinline__ uint32_t smem_u32(const void* p) {
    uint32_t a;
    asm("{ .reg .u64 t; cvta.to.shared.u64 t, %1; cvt.u32.u64 %0, t; }" : "=r"(a) : "l"(p));
    return a;
}
__device__ __forceinline__ void cpa16(uint32_t saddr, const void* g) {
    asm volatile("cp.async.cg.shared.global [%0], [%1], 16;" :: "r"(saddr), "l"(g));
}
__device__ __forceinline__ void cpa_commit() { asm volatile("cp.async.commit_group;" ::: "memory"); }
__device__ __forceinline__ void cpa_wait0()  { asm volatile("cp.async.wait_group 0;" ::: "memory"); }
__device__ __forceinline__ void cpa_wait1()  { asm volatile("cp.async.wait_group 1;" ::: "memory"); }
__device__ __forceinline__ void cpa_wait2()  { asm volatile("cp.async.wait_group 2;" ::: "memory"); }

// ---------------- prep ----------------
__global__ void __launch_bounds__(256) k_prep(const float* __restrict__ f) {
    __shared__ float t[32][33];
    int n0 = blockIdx.x * 32, d0 = blockIdx.y * 32;
    int tx = threadIdx.x, ty = threadIdx.y;
    #pragma unroll
    for (int i = ty; i < 32; i += 8) {
        float v = f[(size_t)(n0 + i) * DF + d0 + tx];
        t[i][tx] = v;
        g_cat[(size_t)(n0 + i) * KCAT + d0 + tx] = __float2half(v);
    }
    __syncthreads();
    #pragma unroll
    for (int i = ty; i < 32; i += 8)
        g_ftT[(size_t)(d0 + i) * NN + n0 + tx] = __float2half(t[tx][i]);
}

__global__ void __launch_bounds__(256) k_wconv(const float* __restrict__ W) {
    int i = blockIdx.x * 256 + threadIdx.x;
    g_w[i] = __float2half(W[i]);
}

// ================= k_main: split-K slice GEMM (frozen R15) =================
__global__ void __launch_bounds__(512, 1) k_main(const float* __restrict__ adj) {
    extern __shared__ char sm[];
    __half* Abuf = (__half*)sm;
    __half* Bbuf = (__half*)(sm + OFF_BM);

    const int tid = threadIdx.x;
    const int lane = tid & 31;
    const int wid = tid >> 5;
    const int wm = wid >> 2, wn = wid & 3;
    const int m0 = blockIdx.x * 128;
    const int slc = blockIdx.y;
    const int K0 = slc * SLC_ITERS;
    const uint32_t b_u32 = smem_u32(Bbuf);

    wmma::fragment<wmma::accumulator, 16, 16, 16, __half> acc[2][4];
    #pragma unroll
    for (int mi = 0; mi < 2; mi++)
        #pragma unroll
        for (int ni = 0; ni < 4; ni++)
            wmma::fill_fragment(acc[mi][ni], __float2half(0.0f));

    float rowacc[4] = {0.f, 0.f, 0.f, 0.f};
    float4 va[4];

    auto ldgA = [&](int it) {
        int k0 = (K0 + it) * 64;
        #pragma unroll
        for (int j = 0; j < 4; j++) {
            int idx = tid + j * 512;
            int row = idx >> 4, c4 = idx & 15;
            va[j] = *(const float4*)(adj + (size_t)(m0 + row) * NN + k0 + c4 * 4);
        }
    };
    auto stsA = [&](int buf) {
        __half* At = Abuf + buf * 128 * ASTM;
        #pragma unroll
        for (int j = 0; j < 4; j++) {
            int idx = tid + j * 512;
            int row = idx >> 4, c4 = idx & 15;
            float4 v = va[j];
            rowacc[j] += (v.x + v.y) + (v.z + v.w);
            __half2 h0 = __floats2half2_rn(v.x, v.y);
            __half2 h1 = __floats2half2_rn(v.z, v.w);
            uint2 u;
            u.x = *(uint32_t*)&h0;
            u.y = *(uint32_t*)&h1;
            *(uint2*)(At + row * ASTM + c4 * 4) = u;
        }
    };
    auto cpaB = [&](int buf, int it) {
        int k0 = (K0 + it) * 64;
        uint32_t b0 = b_u32 + buf * B_STG;
        #pragma unroll
        for (int j = 0; j < 4; j++) {
            int idx = tid + j * 512;
            int row = idx >> 3, c16 = idx & 7;
            cpa16(b0 + (row * ASTM + c16 * 8) * 2, g_ftT + (size_t)row * NN + k0 + c16 * 8);
        }
    };

    ldgA(0);
    stsA(0);
    ldgA(1);
    cpaB(0, 0); cpa_commit();
    cpaB(1, 1); cpa_commit();

    constexpr int NK = SLC_ITERS;
    int bs = 0, bs2 = 2;

    #pragma unroll 1
    for (int it = 0; it < NK; ++it) {
        int cur = it & 1;
        cpa_wait1();
        __syncthreads();

        if (it + 1 < NK) stsA(cur ^ 1);
        if (it + 2 < NK) {
            ldgA(it + 2);
            cpaB(bs2, it + 2);
        }
        cpa_commit();

        const __half* At = Abuf + cur * 128 * ASTM;
        const __half* Bt = Bbuf + bs * 256 * ASTM;
        #pragma unroll
        for (int ks = 0; ks < 4; ++ks) {
            wmma::fragment<wmma::matrix_a, 16, 16, 16, __half, wmma::row_major> af[2];
            #pragma unroll
            for (int mi = 0; mi < 2; mi++)
                wmma::load_matrix_sync(af[mi], At + (wm * 32 + mi * 16) * ASTM + ks * 16, ASTM);
            #pragma unroll
            for (int ni = 0; ni < 4; ni++) {
                wmma::fragment<wmma::matrix_b, 16, 16, 16, __half, wmma::col_major> bf;
                wmma::load_matrix_sync(bf, Bt + (wn * 64 + ni * 16) * ASTM + ks * 16, ASTM);
                #pragma unroll
                for (int mi = 0; mi < 2; mi++)
                    wmma::mma_sync(acc[mi][ni], af[mi], bf, acc[mi][ni]);
            }
        }
        bs = (bs == 2) ? 0 : bs + 1;
        bs2 = (bs2 == 2) ? 0 : bs2 + 1;
    }
    cpa_wait0();

    #pragma unroll
    for (int j = 0; j < 4; j++) {
        float s = rowacc[j];
        s += __shfl_xor_sync(0xFFFFFFFFu, s, 1);
        s += __shfl_xor_sync(0xFFFFFFFFu, s, 2);
        s += __shfl_xor_sync(0xFFFFFFFFu, s, 4);
        s += __shfl_xor_sync(0xFFFFFFFFu, s, 8);
        int row = (tid + j * 512) >> 4;
        if ((lane & 15) == 0) g_rs[(size_t)slc * NN + m0 + row] = s;
    }

    __half* dst = g_part + ((size_t)slc * NN + m0) * DF;
    #pragma unroll
    for (int mi = 0; mi < 2; mi++)
        #pragma unroll
        for (int ni = 0; ni < 4; ni++)
            wmma::store_matrix_sync(dst + (wm * 32 + mi * 16) * DF + wn * 64 + ni * 16,
                                    acc[mi][ni], DF, wmma::mem_row_major);
}

// ================= k_out: fused 8-way partial reduce + out-GEMM =================
__global__ void __launch_bounds__(256, 2) k_out(float* __restrict__ out) {
    extern __shared__ char sm[];
    __half* Abuf = (__half*)sm;                // [4][64][40]
    __half* Bbuf = (__half*)(sm + OFF_BO);     // [4][256][40]
    float*  siv  = (float*)(sm + OFF_SIV);     // [64] 1/(deg+1)
    float*  stage = (float*)sm;                // epilogue reuse [64][68]

    const int tid = threadIdx.x;
    const int wid = tid >> 5;
    const int wm = wid >> 2, wn = wid & 3;
    const int m0 = blockIdx.x * 64;
    const uint32_t a_u32 = smem_u32(Abuf);
    const uint32_t b_u32 = smem_u32(Bbuf);

    wmma::fragment<wmma::accumulator, 16, 16, 16, float> acc[2][4];
    #pragma unroll
    for (int mi = 0; mi < 2; mi++)
        #pragma unroll
        for (int ni = 0; ni < 4; ni++)
            wmma::fill_fragment(acc[mi][ni], 0.0f);

    // A via cp.async only for it<8 (features); B always
    auto loadTile = [&](int slot, int it) {
        int k0 = it * 32;
        if (it < 8) {
            int row = tid >> 2, c8 = tid & 3;
            cpa16(a_u32 + slot * AO_STG + (row * AST + c8 * 8) * 2,
                  g_cat + (size_t)(m0 + row) * KCAT + k0 + c8 * 8);
        }
        #pragma unroll
        for (int j = 0; j < 4; j++) {
            int idx = tid + j * 256;
            int row = idx >> 2, c8 = idx & 3;
            cpa16(b_u32 + slot * BO_STG + (row * AST + c8 * 8) * 2,
                  g_w + (size_t)row * KCAT + k0 + c8 * 8);
        }
    };

    // A via LDG-reduce-STS for it>=8: neigh tile = sum_slices(g_part)*siv
    auto reduceTile = [&](int slot, int it) {
        int r = tid >> 2, c8 = tid & 3;                       // 64 rows x 4 chunks of 8 halves
        int col = (it - 8) * 32 + c8 * 8;
        const __half* base = g_part + (size_t)(m0 + r) * DF + col;
        float s[8] = {0.f, 0.f, 0.f, 0.f, 0.f, 0.f, 0.f, 0.f};
        #pragma unroll
        for (int sl = 0; sl < NSLC; sl++) {                   // fixed order: deterministic
            uint4 u = *(const uint4*)(base + (size_t)sl * NN * DF);
            __half2 a = *(__half2*)&u.x, b = *(__half2*)&u.y;
            __half2 c = *(__half2*)&u.z, d = *(__half2*)&u.w;
            s[0] += __half2float(__low2half(a)); s[1] += __half2float(__high2half(a));
            s[2] += __half2float(__low2half(b)); s[3] += __half2float(__high2half(b));
            s[4] += __half2float(__low2half(c)); s[5] += __half2float(__high2half(c));
            s[6] += __half2float(__low2half(d)); s[7] += __half2float(__high2half(d));
        }
        float iv = siv[r];
        __half2 h0 = __floats2half2_rn(s[0] * iv, s[1] * iv);
        __half2 h1 = __floats2half2_rn(s[2] * iv, s[3] * iv);
        __half2 h2 = __floats2half2_rn(s[4] * iv, s[5] * iv);
        __half2 h3 = __floats2half2_rn(s[6] * iv, s[7] * iv);
        uint4 o;
        o.x = *(uint32_t*)&h0; o.y = *(uint32_t*)&h1;
        o.z = *(uint32_t*)&h2; o.w = *(uint32_t*)&h3;
        *(uint4*)((char*)sm + slot * AO_STG + (r * AST + c8 * 8) * 2) = o;
    };

    // prologue: siv + first 3 tiles (all it<8)
    if (tid < 64) {
        float s = 0.f;
        #pragma unroll
        for (int sl = 0; sl < NSLC; sl++) s += g_rs[(size_t)sl * NN + m0 + tid];
        siv[tid] = 1.0f / (s + 1.0f);
    }
    loadTile(0, 0); cpa_commit();
    loadTile(1, 1); cpa_commit();
    loadTile(2, 2); cpa_commit();
    __syncthreads();  // siv visible before any reduceTile

    constexpr int NK = KCAT / 32;  // 16
    #pragma unroll 1
    for (int it = 0; it < NK; ++it) {
        int cur = it & 3;
        cpa_wait2();       // B(it) (and A(it) if cp.async) landed
        __syncthreads();   // slot (it+3)&3 free; tile(it) visible (STS-filled A too)

        if (it + 3 < NK) { loadTile((it + 3) & 3, it + 3); cpa_commit(); }

        const __half* At = Abuf + cur * 64 * AST;
        const __half* Bt = Bbuf + cur * 256 * AST;
        #pragma unroll
        for (int ks = 0; ks < 2; ++ks) {
            wmma::fragment<wmma::matrix_a, 16, 16, 16, __half, wmma::row_major> af[2];
            #pragma unroll
            for (int mi = 0; mi < 2; mi++)
                wmma::load_matrix_sync(af[mi], At + (wm * 32 + mi * 16) * AST + ks * 16, AST);
            #pragma unroll
            for (int ni = 0; ni < 4; ni++) {
                wmma::fragment<wmma::matrix_b, 16, 16, 16, __half, wmma::col_major> bf;
                wmma::load_matrix_sync(bf, Bt + (wn * 64 + ni * 16) * AST + ks * 16, AST);
                #pragma unroll
                for (int mi = 0; mi < 2; mi++)
                    wmma::mma_sync(acc[mi][ni], af[mi], bf, acc[mi][ni]);
            }
        }

        // fill A slot (it+3) by reduction AFTER MMAs (LDG latency overlaps next iters)
        if (it + 3 < NK && it + 3 >= 8) reduceTile((it + 3) & 3, it + 3);
    }
    cpa_wait0();
    __syncthreads();

    #pragma unroll 1
    for (int p = 0; p < 4; p++) {
        if (wn == p) {
            #pragma unroll
            for (int mi = 0; mi < 2; mi++)
                #pragma unroll
                for (int ni = 0; ni < 4; ni++)
                    wmma::store_matrix_sync(stage + (wm * 32 + mi * 16) * SST + ni * 16,
                                            acc[mi][ni], SST, wmma::mem_row_major);
        }
        __syncthreads();
        #pragma unroll
        for (int j = 0; j < 16; j++) {
            int idx = tid + j * 256;
            int r = idx >> 6, c = idx & 63;
            out[(size_t)(m0 + r) * DF + p * 64 + c] = stage[r * SST + c];
        }
        __syncthreads();
    }
}

// ---------------- launch ----------------
extern "C" void kernel_launch(void* const* d_in, const int* in_sizes, int n_in,
                              void* d_out, int out_size) {
    const float* features = nullptr;
    const float* adj = nullptr;
    const float* W = nullptr;
    for (int i = 0; i < n_in; i++) {
        if (in_sizes[i] == NN * NN) adj = (const float*)d_in[i];
        else if (in_sizes[i] == NN * DF) features = (const float*)d_in[i];
        else if (in_sizes[i] == DF * KCAT) W = (const float*)d_in[i];
    }
    float* out = (float*)d_out;

    cudaFuncSetAttribute(k_main, cudaFuncAttributeMaxDynamicSharedMemorySize, SMEM_MAIN);
    cudaFuncSetAttribute(k_out,  cudaFuncAttributeMaxDynamicSharedMemorySize, SMEM_OUT);

    // k_out now at capture slot 3
    k_prep<<<dim3(NN / 32, DF / 32), dim3(32, 8)>>>(features);
    k_wconv<<<(DF * KCAT) / 256, 256>>>(W);
    k_main<<<dim3(NN / 128, NSLC), 512, SMEM_MAIN>>>(adj);
    k_out<<<NN / 64, 256, SMEM_OUT>>>(out);
}